// round 13
// baseline (speedup 1.0000x reference)
#include <cuda_runtime.h>
#include <math.h>

// ---------------------------------------------------------------------------
// CrossMambaBlock  —  fp32 baseline, channel-major layouts, chunked scan
// B=2, D_MODEL=128, H=W=96 (L=9216), D_INNER=256, D_STATE=16, D_CONV=4, DT_RANK=8
// ---------------------------------------------------------------------------

#define B_    2
#define CM    128
#define HH    96
#define WW    96
#define LL    (HH*WW)        // 9216
#define DI    256
#define DS    16
#define DR    8
#define NSEG  32
#define SEG   (LL/NSEG)      // 288
#define PXT   64
#define XSS   (PXT+4)        // 68  (keeps float4 smem loads 16B-aligned, no conflicts)

// ---- scratch (device globals; allocation-free rule) ----
__device__ __align__(16) float g_qpre [B_*CM*LL];
__device__ __align__(16) float g_kvpre[B_*2*CM*LL];
__device__ __align__(16) float g_fused[B_*CM*LL];
__device__ __align__(16) float g_v    [B_*CM*LL];
__device__ __align__(16) float g_xmpre[B_*DI*LL];
__device__ __align__(16) float g_z    [B_*DI*LL];
__device__ __align__(16) float g_xm   [B_*DI*LL];
__device__ __align__(16) float g_xdbl [B_*40*LL];
__device__ __align__(16) float g_dt   [B_*DI*LL];
__device__ __align__(16) float g_Bm   [B_*LL*DS];
__device__ __align__(16) float g_Cm   [B_*LL*DS];
__device__ __align__(16) float g_y    [B_*DI*LL];
__device__ __align__(16) float g_hend [B_*DI*NSEG*DS];
__device__ __align__(16) float g_h0   [B_*DI*NSEG*DS];
__device__ __align__(16) float g_sumdt[B_*DI*NSEG];
__device__ __align__(16) float g_Wf   [CM*(DI+CM)];

// ---------------------------------------------------------------------------
// Generic pointwise (1x1) conv / GEMM:  out[b,o,l] = sum_c w[o,c] * in[b,c,l]
// Register-tiled 4px x 4out, float4 weight + smem loads -> FFMA-bound.
// in = concat(in0[CIN0], in1[CIN1]); out split at SPLIT into out0/out1.
// ---------------------------------------------------------------------------
template<int CIN0, int CIN1, int COUT, int SPLIT>
__global__ __launch_bounds__(256) void pw_kernel(
    const float* __restrict__ in0, const float* __restrict__ in1,
    const float* __restrict__ w,
    float* __restrict__ out0, float* __restrict__ out1)
{
    constexpr int CIN = CIN0 + CIN1;
    extern __shared__ float Xs[];           // [CIN][XSS]
    const int b  = blockIdx.y;
    const int p0 = blockIdx.x * PXT;
    const int tid = threadIdx.x;

    for (int i = tid; i < CIN*PXT; i += 256) {
        const int c  = i >> 6;
        const int px = i & 63;
        float v;
        if (CIN1 > 0 && c >= CIN0)
            v = in1[(b*CIN1 + (c - CIN0))*LL + p0 + px];
        else
            v = in0[(b*CIN0 + c)*LL + p0 + px];
        Xs[c*XSS + px] = v;
    }
    __syncthreads();

    const int px4  = (tid & 15) * 4;
    const int orow = tid >> 4;              // 0..15

    for (int ob = orow*4; ob < COUT; ob += 64) {
        float acc[4][4];
        #pragma unroll
        for (int j = 0; j < 4; ++j)
            acc[j][0] = acc[j][1] = acc[j][2] = acc[j][3] = 0.f;

        for (int c = 0; c < CIN; c += 4) {
            float4 wv[4];
            #pragma unroll
            for (int j = 0; j < 4; ++j)
                wv[j] = *(const float4*)&w[(ob + j)*CIN + c];
            #pragma unroll
            for (int cc = 0; cc < 4; ++cc) {
                float4 xv = *(const float4*)&Xs[(c + cc)*XSS + px4];
                #pragma unroll
                for (int j = 0; j < 4; ++j) {
                    float wj = (cc == 0) ? wv[j].x : (cc == 1) ? wv[j].y
                             : (cc == 2) ? wv[j].z : wv[j].w;
                    acc[j][0] += wj * xv.x;
                    acc[j][1] += wj * xv.y;
                    acc[j][2] += wj * xv.z;
                    acc[j][3] += wj * xv.w;
                }
            }
        }
        #pragma unroll
        for (int j = 0; j < 4; ++j) {
            const int o = ob + j;
            float* dst;
            if (o < SPLIT) dst = &out0[(b*SPLIT + o)*LL + p0 + px4];
            else           dst = &out1[(b*(COUT-SPLIT) + (o-SPLIT))*LL + p0 + px4];
            *(float4*)dst = make_float4(acc[j][0], acc[j][1], acc[j][2], acc[j][3]);
        }
    }
}

// ---------------------------------------------------------------------------
// 3x3 depthwise on q (128ch) and kv (256ch); fused = dw3(q)+dw3(k); v = dw3(v)
// ---------------------------------------------------------------------------
__global__ void dw3_fused_kernel(const float* __restrict__ wqdw,
                                 const float* __restrict__ wkvdw)
{
    int idx = blockIdx.x * blockDim.x + threadIdx.x;
    if (idx >= B_*2*CM*LL) return;
    const int l = idx % LL;
    const int c = (idx / LL) % (2*CM);
    const int b = idx / (LL*2*CM);
    const int h = l / WW, w = l % WW;

    const float* src = g_kvpre + (b*2*CM + c)*LL;
    const float* wk  = wkvdw + c*9;
    float acc = 0.f;
    #pragma unroll
    for (int i = 0; i < 3; ++i) {
        int hh = h - 1 + i;
        if (hh < 0 || hh >= HH) continue;
        #pragma unroll
        for (int j = 0; j < 3; ++j) {
            int w2 = w - 1 + j;
            if (w2 < 0 || w2 >= WW) continue;
            acc += wk[i*3+j] * src[hh*WW + w2];
        }
    }
    if (c < CM) {
        const float* sq = g_qpre + (b*CM + c)*LL;
        const float* wq = wqdw + c*9;
        float accq = 0.f;
        #pragma unroll
        for (int i = 0; i < 3; ++i) {
            int hh = h - 1 + i;
            if (hh < 0 || hh >= HH) continue;
            #pragma unroll
            for (int j = 0; j < 3; ++j) {
                int w2 = w - 1 + j;
                if (w2 < 0 || w2 >= WW) continue;
                accq += wq[i*3+j] * sq[hh*WW + w2];
            }
        }
        g_fused[(b*CM + c)*LL + l] = acc + accq;
    } else {
        g_v[(b*CM + (c-CM))*LL + l] = acc;
    }
}

// ---------------------------------------------------------------------------
// Causal depthwise conv1d (D_CONV=4) + SiLU
// ---------------------------------------------------------------------------
__global__ void conv1d_silu_kernel(const float* __restrict__ wconv,
                                   const float* __restrict__ bconv)
{
    int idx = blockIdx.x * blockDim.x + threadIdx.x;
    if (idx >= B_*DI*LL) return;
    const int l = idx % LL;
    const int d = (idx / LL) % DI;
    const int b = idx / (LL*DI);
    const float* src = g_xmpre + (b*DI + d)*LL;
    float acc = bconv[d];
    #pragma unroll
    for (int k = 0; k < 4; ++k) {
        int t = l - 3 + k;
        if (t >= 0) acc += wconv[d*4 + k] * src[t];
    }
    g_xm[idx] = acc * (1.f / (1.f + __expf(-acc)));   // silu
}

// ---------------------------------------------------------------------------
// dt = softplus(xdbl[:,:8] @ w_dt.T + b_dt);  Bm/Cm = slices of xdbl
// ---------------------------------------------------------------------------
__global__ __launch_bounds__(256) void dtbc_kernel(const float* __restrict__ wdt,
                                                   const float* __restrict__ bdt)
{
    __shared__ float ws[DI*DR];
    __shared__ float bs[DI];
    for (int i = threadIdx.x; i < DI*DR; i += 256) ws[i] = wdt[i];
    for (int i = threadIdx.x; i < DI;    i += 256) bs[i] = bdt[i];
    __syncthreads();

    int idx = blockIdx.x * 256 + threadIdx.x;
    if (idx >= B_*LL) return;
    const int l = idx % LL, b = idx / LL;

    float xr[DR];
    #pragma unroll
    for (int r = 0; r < DR; ++r) xr[r] = g_xdbl[(b*40 + r)*LL + l];

    for (int j = 0; j < DI; ++j) {
        float s = bs[j];
        #pragma unroll
        for (int r = 0; r < DR; ++r) s += ws[j*DR + r] * xr[r];
        float dtv = (s > 20.f) ? s : log1pf(__expf(s));
        g_dt[(b*DI + j)*LL + l] = dtv;
    }
    #pragma unroll
    for (int i = 0; i < DS; ++i)
        g_Bm[(b*LL + l)*DS + i] = g_xdbl[(b*40 + 8 + i)*LL + l];
    #pragma unroll
    for (int i = 0; i < DS; ++i)
        g_Cm[(b*LL + l)*DS + i] = g_xdbl[(b*40 + 24 + i)*LL + l];
}

// ---------------------------------------------------------------------------
// Chunked selective scan. a_t = exp(A_n*dt_t); h = a*h + dt*xm*B;  y = <h,C>
// Phase A: per-segment local scan (h0=0) -> h_end, sum(dt)
// Phase B: combine segments:  prod(a) over segment = exp(A_n * sum_dt)
// Phase C: rescan with correct h0, reduce over states, gate + skip
// ---------------------------------------------------------------------------
__global__ void scanA_kernel(const float* __restrict__ A_log)
{
    int tid = blockIdx.x * blockDim.x + threadIdx.x;
    if (tid >= B_*DI*NSEG*DS) return;
    const int n = tid & 15;
    const int g = tid >> 4;
    const int s = g % NSEG;
    const int d = (g / NSEG) % DI;
    const int b = g / (NSEG*DI);

    const float An = -__expf(A_log[d*DS + n]);
    const float* dtp = g_dt + (b*DI + d)*LL + s*SEG;
    const float* xmp = g_xm + (b*DI + d)*LL + s*SEG;
    const float* Bp  = g_Bm + (b*LL + s*SEG)*DS + n;

    float h = 0.f, sdt = 0.f;
    #pragma unroll 4
    for (int t = 0; t < SEG; ++t) {
        float dtv = dtp[t];
        float a   = __expf(An * dtv);
        h = a*h + dtv * xmp[t] * Bp[t*DS];
        sdt += dtv;
    }
    g_hend[g*DS + n] = h;
    if (n == 0) g_sumdt[g] = sdt;
}

__global__ void scanB_kernel(const float* __restrict__ A_log)
{
    int tid = blockIdx.x * blockDim.x + threadIdx.x;
    if (tid >= B_*DI*DS) return;
    const int n  = tid & 15;
    const int bd = tid >> 4;
    const int d  = bd % DI;
    const float An = -__expf(A_log[d*DS + n]);
    const int base = bd * NSEG;

    float h = 0.f;
    for (int s = 0; s < NSEG; ++s) {
        g_h0[(base + s)*DS + n] = h;
        float aseg = __expf(An * g_sumdt[base + s]);
        h = aseg*h + g_hend[(base + s)*DS + n];
    }
}

__global__ void scanC_kernel(const float* __restrict__ A_log,
                             const float* __restrict__ D_skip)
{
    int tid = blockIdx.x * blockDim.x + threadIdx.x;
    if (tid >= B_*DI*NSEG*DS) return;
    const int n = tid & 15;
    const int g = tid >> 4;
    const int s = g % NSEG;
    const int d = (g / NSEG) % DI;
    const int b = g / (NSEG*DI);

    const float An = -__expf(A_log[d*DS + n]);
    const float Dv = D_skip[d];
    const int cb = (b*DI + d)*LL + s*SEG;
    const float* dtp = g_dt + cb;
    const float* xmp = g_xm + cb;
    const float* zp  = g_z  + cb;
    const float* Bp  = g_Bm + (b*LL + s*SEG)*DS + n;
    const float* Cp  = g_Cm + (b*LL + s*SEG)*DS + n;
    float* yout = g_y + cb;

    float h = g_h0[g*DS + n];
    for (int t0 = 0; t0 < SEG; t0 += 4) {
        float yv[4];
        #pragma unroll
        for (int u = 0; u < 4; ++u) {
            const int t = t0 + u;
            float dtv = dtp[t];
            float xv  = xmp[t];
            float a   = __expf(An * dtv);
            h = a*h + dtv * xv * Bp[t*DS];
            float p = h * Cp[t*DS];
            p += __shfl_xor_sync(0xffffffffu, p, 1, 16);
            p += __shfl_xor_sync(0xffffffffu, p, 2, 16);
            p += __shfl_xor_sync(0xffffffffu, p, 4, 16);
            p += __shfl_xor_sync(0xffffffffu, p, 8, 16);
            float zv  = zp[t];
            float sig = 1.f / (1.f + __expf(-zv));
            yv[u] = (p + xv * Dv) * (zv * sig);
        }
        if (n == 0)
            *(float4*)(yout + t0) = make_float4(yv[0], yv[1], yv[2], yv[3]);
    }
}

// ---------------------------------------------------------------------------
// Fold output projections:  Wf = [ w_outproj @ w_out  |  w_outproj ]  (128 x 384)
// ---------------------------------------------------------------------------
__global__ void wf_kernel(const float* __restrict__ w_out,
                          const float* __restrict__ w_outproj)
{
    int idx = blockIdx.x * blockDim.x + threadIdx.x;
    if (idx >= CM*(DI+CM)) return;
    const int j = idx % (DI+CM);
    const int o = idx / (DI+CM);
    if (j < DI) {
        float acc = 0.f;
        for (int c = 0; c < CM; ++c)
            acc += w_outproj[o*CM + c] * w_out[c*DI + j];
        g_Wf[idx] = acc;
    } else {
        g_Wf[idx] = w_outproj[o*CM + (j - DI)];
    }
}

// ---------------------------------------------------------------------------
extern "C" void kernel_launch(void* const* d_in, const int* in_sizes, int n_in,
                              void* d_out, int out_size)
{
    (void)in_sizes; (void)n_in; (void)out_size;
    const float* x        = (const float*)d_in[0];
    const float* y        = (const float*)d_in[1];
    const float* w_q      = (const float*)d_in[2];
    const float* w_q_dw   = (const float*)d_in[3];
    const float* w_kv     = (const float*)d_in[4];
    const float* w_kv_dw  = (const float*)d_in[5];
    const float* w_in     = (const float*)d_in[6];
    const float* w_conv   = (const float*)d_in[7];
    const float* b_conv   = (const float*)d_in[8];
    const float* w_xproj  = (const float*)d_in[9];
    const float* w_dt     = (const float*)d_in[10];
    const float* b_dt     = (const float*)d_in[11];
    const float* A_log    = (const float*)d_in[12];
    const float* D_skip   = (const float*)d_in[13];
    const float* w_out    = (const float*)d_in[14];
    const float* w_outproj= (const float*)d_in[15];
    float* out = (float*)d_out;

    float *qpre, *kvpre, *fused, *vv, *xmpre, *zz, *xm, *xdbl, *yy, *Wf;
    cudaGetSymbolAddress((void**)&qpre,  g_qpre);
    cudaGetSymbolAddress((void**)&kvpre, g_kvpre);
    cudaGetSymbolAddress((void**)&fused, g_fused);
    cudaGetSymbolAddress((void**)&vv,    g_v);
    cudaGetSymbolAddress((void**)&xmpre, g_xmpre);
    cudaGetSymbolAddress((void**)&zz,    g_z);
    cudaGetSymbolAddress((void**)&xm,    g_xm);
    cudaGetSymbolAddress((void**)&xdbl,  g_xdbl);
    cudaGetSymbolAddress((void**)&yy,    g_y);
    cudaGetSymbolAddress((void**)&Wf,    g_Wf);

    // dynamic smem attributes for the big-CIN pw instantiations (>48KB)
    cudaFuncSetAttribute((const void*)pw_kernel<256,0,40,40>,
        cudaFuncAttributeMaxDynamicSharedMemorySize, (int)(256*XSS*sizeof(float)));
    cudaFuncSetAttribute((const void*)pw_kernel<256,128,128,128>,
        cudaFuncAttributeMaxDynamicSharedMemorySize, (int)(384*XSS*sizeof(float)));

    const dim3 gpw(LL/PXT, B_);

    // fold output projections
    wf_kernel<<<(CM*(DI+CM)+255)/256, 256>>>(w_out, w_outproj);

    // q = x @ w_q ; kv = y @ w_kv   (1x1 convs)
    pw_kernel<128,0,128,128><<<gpw, 256, 128*XSS*sizeof(float)>>>(x, x, w_q, qpre, qpre);
    pw_kernel<128,0,256,256><<<gpw, 256, 128*XSS*sizeof(float)>>>(y, y, w_kv, kvpre, kvpre);

    // depthwise 3x3 + fuse q+k, extract v
    dw3_fused_kernel<<<(B_*2*CM*LL+255)/256, 256>>>(w_q_dw, w_kv_dw);

    // xz = seq @ w_in.T  -> xm_pre (256) + z (256)
    pw_kernel<128,0,512,256><<<gpw, 256, 128*XSS*sizeof(float)>>>(fused, fused, w_in, xmpre, zz);

    // causal conv1d + silu
    conv1d_silu_kernel<<<(B_*DI*LL+255)/256, 256>>>(w_conv, b_conv);

    // xdbl = xm @ w_xproj.T   (256 -> 40)
    pw_kernel<256,0,40,40><<<gpw, 256, 256*XSS*sizeof(float)>>>(xm, xm, w_xproj, xdbl, xdbl);

    // dt / B / C
    dtbc_kernel<<<(B_*LL)/256, 256>>>(w_dt, b_dt);

    // chunked selective scan
    scanA_kernel<<<(B_*DI*NSEG*DS)/256, 256>>>(A_log);
    scanB_kernel<<<(B_*DI*DS)/256, 256>>>(A_log);
    scanC_kernel<<<(B_*DI*NSEG*DS)/256, 256>>>(A_log, D_skip);

    // out = [y ; v] @ Wf.T
    pw_kernel<256,128,128,128><<<gpw, 256, 384*XSS*sizeof(float)>>>(yy, vv, Wf, out, out);
}

// round 14
// speedup vs baseline: 1.0032x; 1.0032x over previous
#include <cuda_runtime.h>
#include <math.h>

// ---------------------------------------------------------------------------
// CrossMambaBlock  —  fp32 baseline, channel-major layouts, chunked scan
// B=2, D_MODEL=128, H=W=96 (L=9216), D_INNER=256, D_STATE=16, D_CONV=4, DT_RANK=8
// ---------------------------------------------------------------------------

#define B_    2
#define CM    128
#define HH    96
#define WW    96
#define LL    (HH*WW)        // 9216
#define DI    256
#define DS    16
#define DR    8
#define NSEG  32
#define SEG   (LL/NSEG)      // 288
#define PXT   64
#define XSS   (PXT+4)        // 68  (keeps float4 smem loads 16B-aligned, no conflicts)

// ---- scratch (device globals; allocation-free rule) ----
__device__ __align__(16) float g_qpre [B_*CM*LL];
__device__ __align__(16) float g_kvpre[B_*2*CM*LL];
__device__ __align__(16) float g_fused[B_*CM*LL];
__device__ __align__(16) float g_v    [B_*CM*LL];
__device__ __align__(16) float g_xmpre[B_*DI*LL];
__device__ __align__(16) float g_z    [B_*DI*LL];
__device__ __align__(16) float g_xm   [B_*DI*LL];
__device__ __align__(16) float g_xdbl [B_*40*LL];
__device__ __align__(16) float g_dt   [B_*DI*LL];
__device__ __align__(16) float g_Bm   [B_*LL*DS];
__device__ __align__(16) float g_Cm   [B_*LL*DS];
__device__ __align__(16) float g_y    [B_*DI*LL];
__device__ __align__(16) float g_hend [B_*DI*NSEG*DS];
__device__ __align__(16) float g_h0   [B_*DI*NSEG*DS];
__device__ __align__(16) float g_sumdt[B_*DI*NSEG];
__device__ __align__(16) float g_Wf   [CM*(DI+CM)];

// ---------------------------------------------------------------------------
// Generic pointwise (1x1) conv / GEMM:  out[b,o,l] = sum_c w[o,c] * in[b,c,l]
// Register-tiled 4px x 4out, float4 weight + smem loads -> FFMA-bound.
// in = concat(in0[CIN0], in1[CIN1]); out split at SPLIT into out0/out1.
// ---------------------------------------------------------------------------
template<int CIN0, int CIN1, int COUT, int SPLIT>
__global__ __launch_bounds__(256) void pw_kernel(
    const float* __restrict__ in0, const float* __restrict__ in1,
    const float* __restrict__ w,
    float* __restrict__ out0, float* __restrict__ out1)
{
    constexpr int CIN = CIN0 + CIN1;
    extern __shared__ float Xs[];           // [CIN][XSS]
    const int b  = blockIdx.y;
    const int p0 = blockIdx.x * PXT;
    const int tid = threadIdx.x;

    for (int i = tid; i < CIN*PXT; i += 256) {
        const int c  = i >> 6;
        const int px = i & 63;
        float v;
        if (CIN1 > 0 && c >= CIN0)
            v = in1[(b*CIN1 + (c - CIN0))*LL + p0 + px];
        else
            v = in0[(b*CIN0 + c)*LL + p0 + px];
        Xs[c*XSS + px] = v;
    }
    __syncthreads();

    const int px4  = (tid & 15) * 4;
    const int orow = tid >> 4;              // 0..15

    for (int ob = orow*4; ob < COUT; ob += 64) {
        float acc[4][4];
        #pragma unroll
        for (int j = 0; j < 4; ++j)
            acc[j][0] = acc[j][1] = acc[j][2] = acc[j][3] = 0.f;

        for (int c = 0; c < CIN; c += 4) {
            float4 wv[4];
            #pragma unroll
            for (int j = 0; j < 4; ++j)
                wv[j] = *(const float4*)&w[(ob + j)*CIN + c];
            #pragma unroll
            for (int cc = 0; cc < 4; ++cc) {
                float4 xv = *(const float4*)&Xs[(c + cc)*XSS + px4];
                #pragma unroll
                for (int j = 0; j < 4; ++j) {
                    float wj = (cc == 0) ? wv[j].x : (cc == 1) ? wv[j].y
                             : (cc == 2) ? wv[j].z : wv[j].w;
                    acc[j][0] += wj * xv.x;
                    acc[j][1] += wj * xv.y;
                    acc[j][2] += wj * xv.z;
                    acc[j][3] += wj * xv.w;
                }
            }
        }
        #pragma unroll
        for (int j = 0; j < 4; ++j) {
            const int o = ob + j;
            float* dst;
            if (o < SPLIT) dst = &out0[(b*SPLIT + o)*LL + p0 + px4];
            else           dst = &out1[(b*(COUT-SPLIT) + (o-SPLIT))*LL + p0 + px4];
            *(float4*)dst = make_float4(acc[j][0], acc[j][1], acc[j][2], acc[j][3]);
        }
    }
}

// ---------------------------------------------------------------------------
// 3x3 depthwise on q (128ch) and kv (256ch); fused = dw3(q)+dw3(k); v = dw3(v)
// ---------------------------------------------------------------------------
__global__ void dw3_fused_kernel(const float* __restrict__ wqdw,
                                 const float* __restrict__ wkvdw)
{
    int idx = blockIdx.x * blockDim.x + threadIdx.x;
    if (idx >= B_*2*CM*LL) return;
    const int l = idx % LL;
    const int c = (idx / LL) % (2*CM);
    const int b = idx / (LL*2*CM);
    const int h = l / WW, w = l % WW;

    const float* src = g_kvpre + (b*2*CM + c)*LL;
    const float* wk  = wkvdw + c*9;
    float acc = 0.f;
    #pragma unroll
    for (int i = 0; i < 3; ++i) {
        int hh = h - 1 + i;
        if (hh < 0 || hh >= HH) continue;
        #pragma unroll
        for (int j = 0; j < 3; ++j) {
            int w2 = w - 1 + j;
            if (w2 < 0 || w2 >= WW) continue;
            acc += wk[i*3+j] * src[hh*WW + w2];
        }
    }
    if (c < CM) {
        const float* sq = g_qpre + (b*CM + c)*LL;
        const float* wq = wqdw + c*9;
        float accq = 0.f;
        #pragma unroll
        for (int i = 0; i < 3; ++i) {
            int hh = h - 1 + i;
            if (hh < 0 || hh >= HH) continue;
            #pragma unroll
            for (int j = 0; j < 3; ++j) {
                int w2 = w - 1 + j;
                if (w2 < 0 || w2 >= WW) continue;
                accq += wq[i*3+j] * sq[hh*WW + w2];
            }
        }
        g_fused[(b*CM + c)*LL + l] = acc + accq;
    } else {
        g_v[(b*CM + (c-CM))*LL + l] = acc;
    }
}

// ---------------------------------------------------------------------------
// Causal depthwise conv1d (D_CONV=4) + SiLU
// ---------------------------------------------------------------------------
__global__ void conv1d_silu_kernel(const float* __restrict__ wconv,
                                   const float* __restrict__ bconv)
{
    int idx = blockIdx.x * blockDim.x + threadIdx.x;
    if (idx >= B_*DI*LL) return;
    const int l = idx % LL;
    const int d = (idx / LL) % DI;
    const int b = idx / (LL*DI);
    const float* src = g_xmpre + (b*DI + d)*LL;
    float acc = bconv[d];
    #pragma unroll
    for (int k = 0; k < 4; ++k) {
        int t = l - 3 + k;
        if (t >= 0) acc += wconv[d*4 + k] * src[t];
    }
    g_xm[idx] = acc * (1.f / (1.f + __expf(-acc)));   // silu
}

// ---------------------------------------------------------------------------
// dt = softplus(xdbl[:,:8] @ w_dt.T + b_dt);  Bm/Cm = slices of xdbl
// ---------------------------------------------------------------------------
__global__ __launch_bounds__(256) void dtbc_kernel(const float* __restrict__ wdt,
                                                   const float* __restrict__ bdt)
{
    __shared__ float ws[DI*DR];
    __shared__ float bs[DI];
    for (int i = threadIdx.x; i < DI*DR; i += 256) ws[i] = wdt[i];
    for (int i = threadIdx.x; i < DI;    i += 256) bs[i] = bdt[i];
    __syncthreads();

    int idx = blockIdx.x * 256 + threadIdx.x;
    if (idx >= B_*LL) return;
    const int l = idx % LL, b = idx / LL;

    float xr[DR];
    #pragma unroll
    for (int r = 0; r < DR; ++r) xr[r] = g_xdbl[(b*40 + r)*LL + l];

    for (int j = 0; j < DI; ++j) {
        float s = bs[j];
        #pragma unroll
        for (int r = 0; r < DR; ++r) s += ws[j*DR + r] * xr[r];
        float dtv = (s > 20.f) ? s : log1pf(__expf(s));
        g_dt[(b*DI + j)*LL + l] = dtv;
    }
    #pragma unroll
    for (int i = 0; i < DS; ++i)
        g_Bm[(b*LL + l)*DS + i] = g_xdbl[(b*40 + 8 + i)*LL + l];
    #pragma unroll
    for (int i = 0; i < DS; ++i)
        g_Cm[(b*LL + l)*DS + i] = g_xdbl[(b*40 + 24 + i)*LL + l];
}

// ---------------------------------------------------------------------------
// Chunked selective scan. a_t = exp(A_n*dt_t); h = a*h + dt*xm*B;  y = <h,C>
// Phase A: per-segment local scan (h0=0) -> h_end, sum(dt)
// Phase B: combine segments:  prod(a) over segment = exp(A_n * sum_dt)
// Phase C: rescan with correct h0, reduce over states, gate + skip
// ---------------------------------------------------------------------------
__global__ void scanA_kernel(const float* __restrict__ A_log)
{
    int tid = blockIdx.x * blockDim.x + threadIdx.x;
    if (tid >= B_*DI*NSEG*DS) return;
    const int n = tid & 15;
    const int g = tid >> 4;
    const int s = g % NSEG;
    const int d = (g / NSEG) % DI;
    const int b = g / (NSEG*DI);

    const float An = -__expf(A_log[d*DS + n]);
    const float* dtp = g_dt + (b*DI + d)*LL + s*SEG;
    const float* xmp = g_xm + (b*DI + d)*LL + s*SEG;
    const float* Bp  = g_Bm + (b*LL + s*SEG)*DS + n;

    float h = 0.f, sdt = 0.f;
    #pragma unroll 4
    for (int t = 0; t < SEG; ++t) {
        float dtv = dtp[t];
        float a   = __expf(An * dtv);
        h = a*h + dtv * xmp[t] * Bp[t*DS];
        sdt += dtv;
    }
    g_hend[g*DS + n] = h;
    if (n == 0) g_sumdt[g] = sdt;
}

__global__ void scanB_kernel(const float* __restrict__ A_log)
{
    int tid = blockIdx.x * blockDim.x + threadIdx.x;
    if (tid >= B_*DI*DS) return;
    const int n  = tid & 15;
    const int bd = tid >> 4;
    const int d  = bd % DI;
    const float An = -__expf(A_log[d*DS + n]);
    const int base = bd * NSEG;

    float h = 0.f;
    for (int s = 0; s < NSEG; ++s) {
        g_h0[(base + s)*DS + n] = h;
        float aseg = __expf(An * g_sumdt[base + s]);
        h = aseg*h + g_hend[(base + s)*DS + n];
    }
}

__global__ void scanC_kernel(const float* __restrict__ A_log,
                             const float* __restrict__ D_skip)
{
    int tid = blockIdx.x * blockDim.x + threadIdx.x;
    if (tid >= B_*DI*NSEG*DS) return;
    const int n = tid & 15;
    const int g = tid >> 4;
    const int s = g % NSEG;
    const int d = (g / NSEG) % DI;
    const int b = g / (NSEG*DI);

    const float An = -__expf(A_log[d*DS + n]);
    const float Dv = D_skip[d];
    const int cb = (b*DI + d)*LL + s*SEG;
    const float* dtp = g_dt + cb;
    const float* xmp = g_xm + cb;
    const float* zp  = g_z  + cb;
    const float* Bp  = g_Bm + (b*LL + s*SEG)*DS + n;
    const float* Cp  = g_Cm + (b*LL + s*SEG)*DS + n;
    float* yout = g_y + cb;

    float h = g_h0[g*DS + n];
    for (int t0 = 0; t0 < SEG; t0 += 4) {
        float yv[4];
        #pragma unroll
        for (int u = 0; u < 4; ++u) {
            const int t = t0 + u;
            float dtv = dtp[t];
            float xv  = xmp[t];
            float a   = __expf(An * dtv);
            h = a*h + dtv * xv * Bp[t*DS];
            float p = h * Cp[t*DS];
            p += __shfl_xor_sync(0xffffffffu, p, 1, 16);
            p += __shfl_xor_sync(0xffffffffu, p, 2, 16);
            p += __shfl_xor_sync(0xffffffffu, p, 4, 16);
            p += __shfl_xor_sync(0xffffffffu, p, 8, 16);
            float zv  = zp[t];
            float sig = 1.f / (1.f + __expf(-zv));
            yv[u] = (p + xv * Dv) * (zv * sig);
        }
        if (n == 0)
            *(float4*)(yout + t0) = make_float4(yv[0], yv[1], yv[2], yv[3]);
    }
}

// ---------------------------------------------------------------------------
// Fold output projections:  Wf = [ w_outproj @ w_out  |  w_outproj ]  (128 x 384)
// ---------------------------------------------------------------------------
__global__ void wf_kernel(const float* __restrict__ w_out,
                          const float* __restrict__ w_outproj)
{
    int idx = blockIdx.x * blockDim.x + threadIdx.x;
    if (idx >= CM*(DI+CM)) return;
    const int j = idx % (DI+CM);
    const int o = idx / (DI+CM);
    if (j < DI) {
        float acc = 0.f;
        for (int c = 0; c < CM; ++c)
            acc += w_outproj[o*CM + c] * w_out[c*DI + j];
        g_Wf[idx] = acc;
    } else {
        g_Wf[idx] = w_outproj[o*CM + (j - DI)];
    }
}

// ---------------------------------------------------------------------------
extern "C" void kernel_launch(void* const* d_in, const int* in_sizes, int n_in,
                              void* d_out, int out_size)
{
    (void)in_sizes; (void)n_in; (void)out_size;
    const float* x        = (const float*)d_in[0];
    const float* y        = (const float*)d_in[1];
    const float* w_q      = (const float*)d_in[2];
    const float* w_q_dw   = (const float*)d_in[3];
    const float* w_kv     = (const float*)d_in[4];
    const float* w_kv_dw  = (const float*)d_in[5];
    const float* w_in     = (const float*)d_in[6];
    const float* w_conv   = (const float*)d_in[7];
    const float* b_conv   = (const float*)d_in[8];
    const float* w_xproj  = (const float*)d_in[9];
    const float* w_dt     = (const float*)d_in[10];
    const float* b_dt     = (const float*)d_in[11];
    const float* A_log    = (const float*)d_in[12];
    const float* D_skip   = (const float*)d_in[13];
    const float* w_out    = (const float*)d_in[14];
    const float* w_outproj= (const float*)d_in[15];
    float* out = (float*)d_out;

    float *qpre, *kvpre, *fused, *vv, *xmpre, *zz, *xm, *xdbl, *yy, *Wf;
    cudaGetSymbolAddress((void**)&qpre,  g_qpre);
    cudaGetSymbolAddress((void**)&kvpre, g_kvpre);
    cudaGetSymbolAddress((void**)&fused, g_fused);
    cudaGetSymbolAddress((void**)&vv,    g_v);
    cudaGetSymbolAddress((void**)&xmpre, g_xmpre);
    cudaGetSymbolAddress((void**)&zz,    g_z);
    cudaGetSymbolAddress((void**)&xm,    g_xm);
    cudaGetSymbolAddress((void**)&xdbl,  g_xdbl);
    cudaGetSymbolAddress((void**)&yy,    g_y);
    cudaGetSymbolAddress((void**)&Wf,    g_Wf);

    // dynamic smem attributes for the big-CIN pw instantiations (>48KB)
    cudaFuncSetAttribute((const void*)pw_kernel<256,0,40,40>,
        cudaFuncAttributeMaxDynamicSharedMemorySize, (int)(256*XSS*sizeof(float)));
    cudaFuncSetAttribute((const void*)pw_kernel<256,128,128,128>,
        cudaFuncAttributeMaxDynamicSharedMemorySize, (int)(384*XSS*sizeof(float)));

    const dim3 gpw(LL/PXT, B_);

    // fold output projections
    wf_kernel<<<(CM*(DI+CM)+255)/256, 256>>>(w_out, w_outproj);

    // q = x @ w_q ; kv = y @ w_kv   (1x1 convs)
    pw_kernel<128,0,128,128><<<gpw, 256, 128*XSS*sizeof(float)>>>(x, x, w_q, qpre, qpre);
    pw_kernel<128,0,256,256><<<gpw, 256, 128*XSS*sizeof(float)>>>(y, y, w_kv, kvpre, kvpre);

    // depthwise 3x3 + fuse q+k, extract v
    dw3_fused_kernel<<<(B_*2*CM*LL+255)/256, 256>>>(w_q_dw, w_kv_dw);

    // xz = seq @ w_in.T  -> xm_pre (256) + z (256)
    pw_kernel<128,0,512,256><<<gpw, 256, 128*XSS*sizeof(float)>>>(fused, fused, w_in, xmpre, zz);

    // causal conv1d + silu
    conv1d_silu_kernel<<<(B_*DI*LL+255)/256, 256>>>(w_conv, b_conv);

    // xdbl = xm @ w_xproj.T   (256 -> 40)
    pw_kernel<256,0,40,40><<<gpw, 256, 256*XSS*sizeof(float)>>>(xm, xm, w_xproj, xdbl, xdbl);

    // dt / B / C
    dtbc_kernel<<<(B_*LL)/256, 256>>>(w_dt, b_dt);

    // chunked selective scan
    scanA_kernel<<<(B_*DI*NSEG*DS)/256, 256>>>(A_log);
    scanB_kernel<<<(B_*DI*DS)/256, 256>>>(A_log);
    scanC_kernel<<<(B_*DI*NSEG*DS)/256, 256>>>(A_log, D_skip);

    // out = [y ; v] @ Wf.T
    pw_kernel<256,128,128,128><<<gpw, 256, 384*XSS*sizeof(float)>>>(yy, vv, Wf, out, out);
}

// round 15
// speedup vs baseline: 1.0401x; 1.0367x over previous
#include <cuda_runtime.h>
#include <math.h>
#include <stdint.h>

// ---------------------------------------------------------------------------
// CrossMambaBlock — fp32 + packed f32x2 FMA, channel-major, chunked scan
// B=2, D_MODEL=128, H=W=96 (L=9216), D_INNER=256, D_STATE=16, D_CONV=4, DT_RANK=8
// ---------------------------------------------------------------------------

#define B_    2
#define CM    128
#define HH    96
#define WW    96
#define LL    (HH*WW)        // 9216
#define DI    256
#define DS    16
#define DR    8
#define NSEG  32
#define SEG   (LL/NSEG)      // 288
#define PXT   64
#define XSS   (PXT+4)        // 68 (row stride 272B = 17*16 -> float4/b64 aligned)

// ---- scratch (device globals; allocation-free rule) ----
__device__ __align__(16) float g_qpre [B_*CM*LL];
__device__ __align__(16) float g_kvpre[B_*2*CM*LL];
__device__ __align__(16) float g_fused[B_*CM*LL];
__device__ __align__(16) float g_v    [B_*CM*LL];
__device__ __align__(16) float g_xmpre[B_*DI*LL];
__device__ __align__(16) float g_z    [B_*DI*LL];
__device__ __align__(16) float g_xm   [B_*DI*LL];
__device__ __align__(16) float g_xdbl [B_*40*LL];
__device__ __align__(16) float g_dt   [B_*DI*LL];
__device__ __align__(16) float g_Bm   [B_*LL*DS];
__device__ __align__(16) float g_Cm   [B_*LL*DS];
__device__ __align__(16) float g_y    [B_*DI*LL];
__device__ __align__(16) float g_hend [B_*DI*NSEG*DS];
__device__ __align__(16) float g_h0   [B_*DI*NSEG*DS];
__device__ __align__(16) float g_sumdt[B_*DI*NSEG];
__device__ __align__(16) float g_Wf   [CM*(DI+CM)];

// ---- packed f32x2 helpers (Blackwell fma.rn.f32x2: 2 FMAs / instruction) ----
__device__ __forceinline__ uint64_t pack2(float v) {
    uint64_t r;
    asm("mov.b64 %0, {%1, %1};" : "=l"(r) : "f"(v));
    return r;
}
__device__ __forceinline__ void fma2(uint64_t& acc, uint64_t a, uint64_t b) {
    asm("fma.rn.f32x2 %0, %1, %2, %0;" : "+l"(acc) : "l"(a), "l"(b));
}
__device__ __forceinline__ float2 unpack2(uint64_t p) {
    float2 f;
    asm("mov.b64 {%0, %1}, %2;" : "=f"(f.x), "=f"(f.y) : "l"(p));
    return f;
}

// ---------------------------------------------------------------------------
// Generic pointwise (1x1) GEMM:  out[b,o,l] = sum_c w[o,c] * in[b,c,l]
// Register-tiled 4px x 4out; inner loop in fma.rn.f32x2 (2 FMA/instr).
// ---------------------------------------------------------------------------
template<int CIN0, int CIN1, int COUT, int SPLIT>
__global__ __launch_bounds__(256) void pw_kernel(
    const float* __restrict__ in0, const float* __restrict__ in1,
    const float* __restrict__ w,
    float* __restrict__ out0, float* __restrict__ out1)
{
    constexpr int CIN = CIN0 + CIN1;
    extern __shared__ float Xs[];           // [CIN][XSS]
    const int b  = blockIdx.y;
    const int p0 = blockIdx.x * PXT;
    const int tid = threadIdx.x;

    for (int i = tid; i < CIN*PXT; i += 256) {
        const int c  = i >> 6;
        const int px = i & 63;
        float v;
        if (CIN1 > 0 && c >= CIN0)
            v = in1[(b*CIN1 + (c - CIN0))*LL + p0 + px];
        else
            v = in0[(b*CIN0 + c)*LL + p0 + px];
        Xs[c*XSS + px] = v;
    }
    __syncthreads();

    const int px4  = (tid & 15) * 4;
    const int orow = tid >> 4;              // 0..15

    for (int ob = orow*4; ob < COUT; ob += 64) {
        uint64_t acc[4][2];
        #pragma unroll
        for (int j = 0; j < 4; ++j) { acc[j][0] = 0ull; acc[j][1] = 0ull; }

        for (int c = 0; c < CIN; c += 4) {
            float4 wv[4];
            #pragma unroll
            for (int j = 0; j < 4; ++j)
                wv[j] = *(const float4*)&w[(ob + j)*CIN + c];
            #pragma unroll
            for (int cc = 0; cc < 4; ++cc) {
                const uint64_t* xp = (const uint64_t*)&Xs[(c + cc)*XSS + px4];
                const uint64_t x0 = xp[0];
                const uint64_t x1 = xp[1];
                #pragma unroll
                for (int j = 0; j < 4; ++j) {
                    float wj = (cc == 0) ? wv[j].x : (cc == 1) ? wv[j].y
                             : (cc == 2) ? wv[j].z : wv[j].w;
                    uint64_t wp = pack2(wj);
                    fma2(acc[j][0], wp, x0);
                    fma2(acc[j][1], wp, x1);
                }
            }
        }
        #pragma unroll
        for (int j = 0; j < 4; ++j) {
            const int o = ob + j;
            float* dst;
            if (o < SPLIT) dst = &out0[(b*SPLIT + o)*LL + p0 + px4];
            else           dst = &out1[(b*(COUT-SPLIT) + (o-SPLIT))*LL + p0 + px4];
            float2 a0 = unpack2(acc[j][0]);
            float2 a1 = unpack2(acc[j][1]);
            *(float4*)dst = make_float4(a0.x, a0.y, a1.x, a1.y);
        }
    }
}

// ---------------------------------------------------------------------------
// 3x3 depthwise, 4 pixels per thread. fused = dw3(q)+dw3(k); v = dw3(v)
// ---------------------------------------------------------------------------
__global__ __launch_bounds__(256) void dw3_fused_kernel(
    const float* __restrict__ wqdw, const float* __restrict__ wkvdw)
{
    int idx = blockIdx.x * blockDim.x + threadIdx.x;   // B*2CM*HH*(WW/4)
    if (idx >= B_*2*CM*HH*(WW/4)) return;
    const int q4 = idx % (WW/4);
    const int h  = (idx / (WW/4)) % HH;
    const int c  = (idx / (WW/4) / HH) % (2*CM);
    const int b  =  idx / (WW/4) / HH / (2*CM);
    const int w0 = q4 * 4;

    float acc[4] = {0.f, 0.f, 0.f, 0.f};
    {
        const float* base = g_kvpre + (b*2*CM + c)*LL;
        const float* wk   = wkvdw + c*9;
        #pragma unroll
        for (int i = 0; i < 3; ++i) {
            const int hh = h - 1 + i;
            if (hh < 0 || hh >= HH) continue;
            const float* row = base + hh*WW;
            float rv[6];
            #pragma unroll
            for (int k = 0; k < 6; ++k) {
                const int wc = w0 - 1 + k;
                rv[k] = (wc >= 0 && wc < WW) ? row[wc] : 0.f;
            }
            #pragma unroll
            for (int p = 0; p < 4; ++p) {
                acc[p] += wk[i*3+0]*rv[p] + wk[i*3+1]*rv[p+1] + wk[i*3+2]*rv[p+2];
            }
        }
    }
    const int l0 = h*WW + w0;
    if (c < CM) {
        const float* base = g_qpre + (b*CM + c)*LL;
        const float* wq   = wqdw + c*9;
        #pragma unroll
        for (int i = 0; i < 3; ++i) {
            const int hh = h - 1 + i;
            if (hh < 0 || hh >= HH) continue;
            const float* row = base + hh*WW;
            float rv[6];
            #pragma unroll
            for (int k = 0; k < 6; ++k) {
                const int wc = w0 - 1 + k;
                rv[k] = (wc >= 0 && wc < WW) ? row[wc] : 0.f;
            }
            #pragma unroll
            for (int p = 0; p < 4; ++p) {
                acc[p] += wq[i*3+0]*rv[p] + wq[i*3+1]*rv[p+1] + wq[i*3+2]*rv[p+2];
            }
        }
        *(float4*)&g_fused[(b*CM + c)*LL + l0] = make_float4(acc[0], acc[1], acc[2], acc[3]);
    } else {
        *(float4*)&g_v[(b*CM + (c-CM))*LL + l0] = make_float4(acc[0], acc[1], acc[2], acc[3]);
    }
}

// ---------------------------------------------------------------------------
// Causal depthwise conv1d (D_CONV=4) + SiLU, 4 px per thread
// ---------------------------------------------------------------------------
__global__ void conv1d_silu_kernel(const float* __restrict__ wconv,
                                   const float* __restrict__ bconv)
{
    int idx = blockIdx.x * blockDim.x + threadIdx.x;   // B*DI*(LL/4)
    if (idx >= B_*DI*(LL/4)) return;
    const int l0 = (idx % (LL/4)) * 4;
    const int d  = (idx / (LL/4)) % DI;
    const int b  =  idx / (LL/4) / DI;
    const float* src = g_xmpre + (b*DI + d)*LL;
    const float bc = bconv[d];
    float wc[4];
    #pragma unroll
    for (int k = 0; k < 4; ++k) wc[k] = wconv[d*4 + k];

    float s[7];
    #pragma unroll
    for (int k = 0; k < 7; ++k) {
        const int t = l0 - 3 + k;
        s[k] = (t >= 0) ? src[t] : 0.f;
    }
    float o[4];
    #pragma unroll
    for (int p = 0; p < 4; ++p) {
        float a = bc + wc[0]*s[p] + wc[1]*s[p+1] + wc[2]*s[p+2] + wc[3]*s[p+3];
        o[p] = a * (1.f / (1.f + __expf(-a)));
    }
    *(float4*)&g_xm[(b*DI + d)*LL + l0] = make_float4(o[0], o[1], o[2], o[3]);
}

// ---------------------------------------------------------------------------
// dt = softplus(xdbl[:,:8] @ w_dt.T + b_dt);  Bm/Cm = slices of xdbl
// ---------------------------------------------------------------------------
__global__ __launch_bounds__(256) void dtbc_kernel(const float* __restrict__ wdt,
                                                   const float* __restrict__ bdt)
{
    __shared__ float ws[DI*DR];
    __shared__ float bs[DI];
    for (int i = threadIdx.x; i < DI*DR; i += 256) ws[i] = wdt[i];
    for (int i = threadIdx.x; i < DI;    i += 256) bs[i] = bdt[i];
    __syncthreads();

    int idx = blockIdx.x * 256 + threadIdx.x;
    if (idx >= B_*LL) return;
    const int l = idx % LL, b = idx / LL;

    float xr[DR];
    #pragma unroll
    for (int r = 0; r < DR; ++r) xr[r] = g_xdbl[(b*40 + r)*LL + l];

    for (int j = 0; j < DI; ++j) {
        float s = bs[j];
        #pragma unroll
        for (int r = 0; r < DR; ++r) s += ws[j*DR + r] * xr[r];
        float dtv = (s > 20.f) ? s : log1pf(__expf(s));
        g_dt[(b*DI + j)*LL + l] = dtv;
    }
    #pragma unroll
    for (int i = 0; i < DS; ++i)
        g_Bm[(b*LL + l)*DS + i] = g_xdbl[(b*40 + 8 + i)*LL + l];
    #pragma unroll
    for (int i = 0; i < DS; ++i)
        g_Cm[(b*LL + l)*DS + i] = g_xdbl[(b*40 + 24 + i)*LL + l];
}

// ---------------------------------------------------------------------------
// Chunked selective scan (3 phases)
// ---------------------------------------------------------------------------
__global__ void scanA_kernel(const float* __restrict__ A_log)
{
    int tid = blockIdx.x * blockDim.x + threadIdx.x;
    if (tid >= B_*DI*NSEG*DS) return;
    const int n = tid & 15;
    const int g = tid >> 4;
    const int s = g % NSEG;
    const int d = (g / NSEG) % DI;
    const int b = g / (NSEG*DI);

    const float An = -__expf(A_log[d*DS + n]);
    const float* dtp = g_dt + (b*DI + d)*LL + s*SEG;
    const float* xmp = g_xm + (b*DI + d)*LL + s*SEG;
    const float* Bp  = g_Bm + (b*LL + s*SEG)*DS + n;

    float h = 0.f, sdt = 0.f;
    #pragma unroll 4
    for (int t = 0; t < SEG; ++t) {
        float dtv = dtp[t];
        float a   = __expf(An * dtv);
        h = a*h + dtv * xmp[t] * Bp[t*DS];
        sdt += dtv;
    }
    g_hend[g*DS + n] = h;
    if (n == 0) g_sumdt[g] = sdt;
}

__global__ void scanB_kernel(const float* __restrict__ A_log)
{
    int tid = blockIdx.x * blockDim.x + threadIdx.x;
    if (tid >= B_*DI*DS) return;
    const int n  = tid & 15;
    const int bd = tid >> 4;
    const int d  = bd % DI;
    const float An = -__expf(A_log[d*DS + n]);
    const int base = bd * NSEG;

    float h = 0.f;
    for (int s = 0; s < NSEG; ++s) {
        g_h0[(base + s)*DS + n] = h;
        float aseg = __expf(An * g_sumdt[base + s]);
        h = aseg*h + g_hend[(base + s)*DS + n];
    }
}

__global__ void scanC_kernel(const float* __restrict__ A_log,
                             const float* __restrict__ D_skip)
{
    int tid = blockIdx.x * blockDim.x + threadIdx.x;
    if (tid >= B_*DI*NSEG*DS) return;
    const int n = tid & 15;
    const int g = tid >> 4;
    const int s = g % NSEG;
    const int d = (g / NSEG) % DI;
    const int b = g / (NSEG*DI);

    const float An = -__expf(A_log[d*DS + n]);
    const float Dv = D_skip[d];
    const int cb = (b*DI + d)*LL + s*SEG;
    const float* dtp = g_dt + cb;
    const float* xmp = g_xm + cb;
    const float* zp  = g_z  + cb;
    const float* Bp  = g_Bm + (b*LL + s*SEG)*DS + n;
    const float* Cp  = g_Cm + (b*LL + s*SEG)*DS + n;
    float* yout = g_y + cb;

    float h = g_h0[g*DS + n];
    for (int t0 = 0; t0 < SEG; t0 += 4) {
        float yv[4];
        #pragma unroll
        for (int u = 0; u < 4; ++u) {
            const int t = t0 + u;
            float dtv = dtp[t];
            float xv  = xmp[t];
            float a   = __expf(An * dtv);
            h = a*h + dtv * xv * Bp[t*DS];
            float p = h * Cp[t*DS];
            p += __shfl_xor_sync(0xffffffffu, p, 1, 16);
            p += __shfl_xor_sync(0xffffffffu, p, 2, 16);
            p += __shfl_xor_sync(0xffffffffu, p, 4, 16);
            p += __shfl_xor_sync(0xffffffffu, p, 8, 16);
            float zv  = zp[t];
            float sig = 1.f / (1.f + __expf(-zv));
            yv[u] = (p + xv * Dv) * (zv * sig);
        }
        if (n == 0)
            *(float4*)(yout + t0) = make_float4(yv[0], yv[1], yv[2], yv[3]);
    }
}

// ---------------------------------------------------------------------------
// Fold output projections:  Wf = [ w_outproj @ w_out | w_outproj ]  (128 x 384)
// ---------------------------------------------------------------------------
__global__ void wf_kernel(const float* __restrict__ w_out,
                          const float* __restrict__ w_outproj)
{
    int idx = blockIdx.x * blockDim.x + threadIdx.x;
    if (idx >= CM*(DI+CM)) return;
    const int j = idx % (DI+CM);
    const int o = idx / (DI+CM);
    if (j < DI) {
        float acc = 0.f;
        for (int c = 0; c < CM; ++c)
            acc += w_outproj[o*CM + c] * w_out[c*DI + j];
        g_Wf[idx] = acc;
    } else {
        g_Wf[idx] = w_outproj[o*CM + (j - DI)];
    }
}

// ---------------------------------------------------------------------------
extern "C" void kernel_launch(void* const* d_in, const int* in_sizes, int n_in,
                              void* d_out, int out_size)
{
    (void)in_sizes; (void)n_in; (void)out_size;
    const float* x        = (const float*)d_in[0];
    const float* y        = (const float*)d_in[1];
    const float* w_q      = (const float*)d_in[2];
    const float* w_q_dw   = (const float*)d_in[3];
    const float* w_kv     = (const float*)d_in[4];
    const float* w_kv_dw  = (const float*)d_in[5];
    const float* w_in     = (const float*)d_in[6];
    const float* w_conv   = (const float*)d_in[7];
    const float* b_conv   = (const float*)d_in[8];
    const float* w_xproj  = (const float*)d_in[9];
    const float* w_dt     = (const float*)d_in[10];
    const float* b_dt     = (const float*)d_in[11];
    const float* A_log    = (const float*)d_in[12];
    const float* D_skip   = (const float*)d_in[13];
    const float* w_out    = (const float*)d_in[14];
    const float* w_outproj= (const float*)d_in[15];
    float* out = (float*)d_out;

    float *qpre, *kvpre, *fused, *vv, *xmpre, *zz, *xm, *xdbl, *yy, *Wf;
    cudaGetSymbolAddress((void**)&qpre,  g_qpre);
    cudaGetSymbolAddress((void**)&kvpre, g_kvpre);
    cudaGetSymbolAddress((void**)&fused, g_fused);
    cudaGetSymbolAddress((void**)&vv,    g_v);
    cudaGetSymbolAddress((void**)&xmpre, g_xmpre);
    cudaGetSymbolAddress((void**)&zz,    g_z);
    cudaGetSymbolAddress((void**)&xm,    g_xm);
    cudaGetSymbolAddress((void**)&xdbl,  g_xdbl);
    cudaGetSymbolAddress((void**)&yy,    g_y);
    cudaGetSymbolAddress((void**)&Wf,    g_Wf);

    cudaFuncSetAttribute((const void*)pw_kernel<256,0,40,40>,
        cudaFuncAttributeMaxDynamicSharedMemorySize, (int)(256*XSS*sizeof(float)));
    cudaFuncSetAttribute((const void*)pw_kernel<256,128,128,128>,
        cudaFuncAttributeMaxDynamicSharedMemorySize, (int)(384*XSS*sizeof(float)));

    const dim3 gpw(LL/PXT, B_);

    // fold output projections
    wf_kernel<<<(CM*(DI+CM)+255)/256, 256>>>(w_out, w_outproj);

    // q = x @ w_q ; kv = y @ w_kv   (1x1 convs)
    pw_kernel<128,0,128,128><<<gpw, 256, 128*XSS*sizeof(float)>>>(x, x, w_q, qpre, qpre);
    pw_kernel<128,0,256,256><<<gpw, 256, 128*XSS*sizeof(float)>>>(y, y, w_kv, kvpre, kvpre);

    // depthwise 3x3 + fuse q+k, extract v
    dw3_fused_kernel<<<(B_*2*CM*HH*(WW/4)+255)/256, 256>>>(w_q_dw, w_kv_dw);

    // xz = seq @ w_in.T  -> xm_pre (256) + z (256)
    pw_kernel<128,0,512,256><<<gpw, 256, 128*XSS*sizeof(float)>>>(fused, fused, w_in, xmpre, zz);

    // causal conv1d + silu
    conv1d_silu_kernel<<<(B_*DI*(LL/4)+255)/256, 256>>>(w_conv, b_conv);

    // xdbl = xm @ w_xproj.T   (256 -> 40)
    pw_kernel<256,0,40,40><<<gpw, 256, 256*XSS*sizeof(float)>>>(xm, xm, w_xproj, xdbl, xdbl);

    // dt / B / C
    dtbc_kernel<<<(B_*LL)/256, 256>>>(w_dt, b_dt);

    // chunked selective scan
    scanA_kernel<<<(B_*DI*NSEG*DS)/256, 256>>>(A_log);
    scanB_kernel<<<(B_*DI*DS)/256, 256>>>(A_log);
    scanC_kernel<<<(B_*DI*NSEG*DS)/256, 256>>>(A_log, D_skip);

    // out = [y ; v] @ Wf.T
    pw_kernel<256,128,128,128><<<gpw, 256, 384*XSS*sizeof(float)>>>(yy, vv, Wf, out, out);
}